// round 2
// baseline (speedup 1.0000x reference)
#include <cuda_runtime.h>
#include <math.h>

#define Bc 2
#define Nc 1024
#define Dc 512
#define Hc 8
#define DHc 64
#define HDc 512
#define FFc 2048
#define Mc (Bc*Nc)     /* 2048 rows */
#define BHc (Bc*Hc)    /* 16 batch-heads */
#define SCALEc 0.125f  /* 64^-0.5 */

// ---------------- device scratch (static allocation; no cudaMalloc allowed) ---------
static __device__ float g_xn[Mc*Dc];
static __device__ float g_qkv[Mc*3*HDc];
static __device__ float g_q[BHc*Nc*DHc];
static __device__ float g_k[BHc*Nc*DHc];
static __device__ float g_v[BHc*Nc*DHc];
static __device__ float g_ws[Mc*HDc];
static __device__ float g_wsr[BHc*Nc*DHc];
static __device__ float g_ac[(size_t)BHc*Nc*Nc];     // scores / dots / attn (in-place)
static __device__ float g_bdraw[(size_t)BHc*Nc*Nc];  // raw BD before rel_shift
static __device__ float g_av[Mc*HDc];
static __device__ float g_h1[Mc*FFc];
static __device__ float g_x[Mc*Dc];
static __device__ float g_xmid[Mc*Dc];

// ---------------- LayerNorm: one block per row (D=512), 128 threads x 4 elems -------
__global__ __launch_bounds__(128) void ln_kernel(
    const float* __restrict__ in, float* __restrict__ out,
    const float* __restrict__ g, const float* __restrict__ bta)
{
    int row = blockIdx.x;
    const float* xr = in + (size_t)row * Dc;
    float* orow = out + (size_t)row * Dc;
    int tid = threadIdx.x;
    float v[4]; float s = 0.f, ss = 0.f;
#pragma unroll
    for (int i = 0; i < 4; i++) {
        v[i] = xr[tid + i*128];
        s += v[i]; ss += v[i]*v[i];
    }
#pragma unroll
    for (int o = 16; o > 0; o >>= 1) {
        s  += __shfl_xor_sync(0xffffffffu, s, o);
        ss += __shfl_xor_sync(0xffffffffu, ss, o);
    }
    __shared__ float sh[8];
    int w = tid >> 5, lane = tid & 31;
    if (lane == 0) { sh[w] = s; sh[4+w] = ss; }
    __syncthreads();
    if (tid == 0) {
        float ts  = sh[0]+sh[1]+sh[2]+sh[3];
        float tss = sh[4]+sh[5]+sh[6]+sh[7];
        sh[0] = ts; sh[1] = tss;
    }
    __syncthreads();
    float mean = sh[0] * (1.f/Dc);
    float var  = sh[1] * (1.f/Dc) - mean*mean;
    float inv  = rsqrtf(var + 1e-5f);
#pragma unroll
    for (int i = 0; i < 4; i++) {
        int c = tid + i*128;
        orow[c] = (v[i]-mean)*inv*g[c] + bta[c];
    }
}

// ---------------- Generic row-major GEMM: C(MxN) = A(MxK) @ B(KxN) ------------------
// 64x64 tile, BK=16, 256 threads, 4x4 microtile.
// mode: 0 plain, 1 +bias(col), 2 +bias+resid, 3 gelu(+bias), 4 accumulate into C
__global__ __launch_bounds__(256) void gemm_kernel(
    const float* __restrict__ A, const float* __restrict__ Bm, float* __restrict__ C,
    int M_, int N_, int K_, const float* __restrict__ bias,
    const float* __restrict__ resid, int mode)
{
    __shared__ float As[16][64];
    __shared__ float Bs[16][64];
    int tid = threadIdx.x;
    int brow = blockIdx.y * 64;
    int bcol = blockIdx.x * 64;
    int tr = tid >> 4, tc = tid & 15;
    int ar = tid >> 2, acg = (tid & 3) * 4;
    int br2 = tid >> 4, bc2 = (tid & 15) * 4;
    float acc[4][4] = {};
    for (int k0 = 0; k0 < K_; k0 += 16) {
        float4 av = *(const float4*)(A + (size_t)(brow + ar) * K_ + k0 + acg);
        As[acg+0][ar] = av.x; As[acg+1][ar] = av.y;
        As[acg+2][ar] = av.z; As[acg+3][ar] = av.w;
        *(float4*)&Bs[br2][bc2] = *(const float4*)(Bm + (size_t)(k0 + br2) * N_ + bcol + bc2);
        __syncthreads();
#pragma unroll
        for (int kk = 0; kk < 16; kk++) {
            float a[4], bv[4];
#pragma unroll
            for (int i = 0; i < 4; i++) a[i] = As[kk][tr*4+i];
#pragma unroll
            for (int j = 0; j < 4; j++) bv[j] = Bs[kk][tc*4+j];
#pragma unroll
            for (int i = 0; i < 4; i++)
#pragma unroll
                for (int j = 0; j < 4; j++)
                    acc[i][j] = fmaf(a[i], bv[j], acc[i][j]);
        }
        __syncthreads();
    }
#pragma unroll
    for (int i = 0; i < 4; i++) {
        int row = brow + tr*4 + i;
#pragma unroll
        for (int j = 0; j < 4; j++) {
            int col = bcol + tc*4 + j;
            size_t off = (size_t)row * N_ + col;
            float v = acc[i][j];
            if (mode == 1)      v += bias[col];
            else if (mode == 2) v += bias[col] + resid[off];
            else if (mode == 3) { v += bias[col];
                                  v = 0.5f * v * (1.0f + erff(v * 0.70710678118654752f)); }
            else if (mode == 4) v += C[off];
            C[off] = v;
        }
    }
}

// ---------------- split qkv -> (b,h,n,d) layouts, q gets +bias_pf -------------------
__global__ void split_qkv_kernel(
    const float* __restrict__ qkv, const float* __restrict__ bias_pf,
    float* __restrict__ q, float* __restrict__ k, float* __restrict__ v)
{
    int idx = blockIdx.x * blockDim.x + threadIdx.x;  // over B*H*N*DH = 1M
    int d = idx & 63;
    int n = (idx >> 6) & (Nc - 1);
    int h = (idx >> 16) & 7;
    int b = idx >> 19;
    size_t src = ((size_t)(b*Nc + n)) * (3*HDc) + h*DHc + d;
    q[idx] = qkv[src] + bias_pf[h*DHc + d];
    k[idx] = qkv[src + HDc];
    v[idx] = qkv[src + 2*HDc];
}

// ---------------- reshape ws (b,n,h*d) -> (b,h,n,d), apply 1/3 ---------------------
__global__ void wsr_kernel(const float* __restrict__ ws, float* __restrict__ wsr)
{
    int idx = blockIdx.x * blockDim.x + threadIdx.x;
    int d = idx & 63;
    int n = (idx >> 6) & (Nc - 1);
    int h = (idx >> 16) & 7;
    int b = idx >> 19;
    wsr[idx] = ws[((size_t)(b*Nc + n)) * HDc + h*DHc + d] * (1.0f/3.0f);
}

// ---------------- batched NT score GEMM: S[bh] = Q[bh] @ K[bh]^T  (1024x64 each) ----
__global__ __launch_bounds__(256) void attn_score_kernel(
    const float* __restrict__ Q, const float* __restrict__ Kt, float* __restrict__ S)
{
    int bh = blockIdx.z;
    const float* Qb = Q + (size_t)bh * Nc * DHc;
    const float* Kb = Kt + (size_t)bh * Nc * DHc;
    float* Sb = S + (size_t)bh * Nc * Nc;
    __shared__ float Qs[16][64];
    __shared__ float Ks[16][64];
    int i0 = blockIdx.y * 64, j0 = blockIdx.x * 64;
    int tid = threadIdx.x;
    int tr = tid >> 4, tc = tid & 15;
    int ar = tid >> 2, acg = (tid & 3) * 4;
    float acc[4][4] = {};
    for (int k0 = 0; k0 < DHc; k0 += 16) {
        float4 qv = *(const float4*)&Qb[(size_t)(i0 + ar) * DHc + k0 + acg];
        Qs[acg+0][ar] = qv.x; Qs[acg+1][ar] = qv.y;
        Qs[acg+2][ar] = qv.z; Qs[acg+3][ar] = qv.w;
        float4 kv = *(const float4*)&Kb[(size_t)(j0 + ar) * DHc + k0 + acg];
        Ks[acg+0][ar] = kv.x; Ks[acg+1][ar] = kv.y;
        Ks[acg+2][ar] = kv.z; Ks[acg+3][ar] = kv.w;
        __syncthreads();
#pragma unroll
        for (int kk = 0; kk < 16; kk++) {
            float a[4], bv[4];
#pragma unroll
            for (int i = 0; i < 4; i++) a[i] = Qs[kk][tr*4+i];
#pragma unroll
            for (int j = 0; j < 4; j++) bv[j] = Ks[kk][tc*4+j];
#pragma unroll
            for (int i = 0; i < 4; i++)
#pragma unroll
                for (int j = 0; j < 4; j++)
                    acc[i][j] = fmaf(a[i], bv[j], acc[i][j]);
        }
        __syncthreads();
    }
#pragma unroll
    for (int i = 0; i < 4; i++)
#pragma unroll
        for (int j = 0; j < 4; j++)
            Sb[(size_t)(i0 + tr*4 + i) * Nc + j0 + tc*4 + j] = acc[i][j];
}

// ---------------- dots = (AC + rel_shift(BDraw)) * SCALE, in-place on AC ------------
__global__ void combine_kernel(float* __restrict__ AC, const float* __restrict__ BD)
{
    size_t idx = (size_t)blockIdx.x * blockDim.x + threadIdx.x;  // 16M
    int j = (int)(idx & (Nc - 1));
    int a = (int)((idx >> 10) & (Nc - 1));
    int bh = (int)(idx >> 20);
    int f = a * Nc + j + Nc;              // rel_shift index math (I=J=N)
    int i2 = f / (Nc + 1);
    int jj = f - i2 * (Nc + 1);
    float bd = (jj == 0) ? 0.f : BD[(size_t)bh * Nc * Nc + (size_t)i2 * Nc + (jj - 1)];
    AC[idx] = (AC[idx] + bd) * SCALEc;
}

// ---------------- softmax over HEADS (8 values, stride N*N) -------------------------
__global__ void softmax_h_kernel(const float* __restrict__ dots, float* __restrict__ attn)
{
    size_t idx = (size_t)blockIdx.x * blockDim.x + threadIdx.x;  // over B*N*N = 2M
    int j = (int)(idx & (Nc - 1));
    int i = (int)((idx >> 10) & (Nc - 1));
    int b = (int)(idx >> 20);
    size_t base = ((size_t)b * Hc) * Nc * Nc + (size_t)i * Nc + j;
    const size_t stride = (size_t)Nc * Nc;
    float m = -1e30f;
    float e[Hc];
#pragma unroll
    for (int h = 0; h < Hc; h++) { float t = dots[base + h*stride]; m = fmaxf(m, t); }
    float s = 0.f;
#pragma unroll
    for (int h = 0; h < Hc; h++) { e[h] = expf(dots[base + h*stride] - m); s += e[h]; }
    float inv = 1.f / s;
#pragma unroll
    for (int h = 0; h < Hc; h++) attn[base + h*stride] = e[h] * inv;
}

// ---------------- O[b,i,h*64+d] = sum_j P[bh,i,j] * V[bh,j,d] -----------------------
__global__ __launch_bounds__(256) void attn_v_kernel(
    const float* __restrict__ P, const float* __restrict__ V, float* __restrict__ O)
{
    int bh = blockIdx.y;
    int bb = bh >> 3, h = bh & 7;
    const float* Pb = P + (size_t)bh * Nc * Nc;
    const float* Vb = V + (size_t)bh * Nc * DHc;
    int i0 = blockIdx.x * 64;
    __shared__ float Ps[16][64];
    __shared__ float Vs[16][64];
    int tid = threadIdx.x;
    int tr = tid >> 4, tc = tid & 15;
    int pr = tid >> 2, pcg = (tid & 3) * 4;
    int vr = tid >> 4, vc = (tid & 15) * 4;
    float acc[4][4] = {};
    for (int k0 = 0; k0 < Nc; k0 += 16) {
        float4 pv = *(const float4*)&Pb[(size_t)(i0 + pr) * Nc + k0 + pcg];
        Ps[pcg+0][pr] = pv.x; Ps[pcg+1][pr] = pv.y;
        Ps[pcg+2][pr] = pv.z; Ps[pcg+3][pr] = pv.w;
        *(float4*)&Vs[vr][vc] = *(const float4*)&Vb[(size_t)(k0 + vr) * DHc + vc];
        __syncthreads();
#pragma unroll
        for (int kk = 0; kk < 16; kk++) {
            float a[4], bv[4];
#pragma unroll
            for (int i = 0; i < 4; i++) a[i] = Ps[kk][tr*4+i];
#pragma unroll
            for (int j = 0; j < 4; j++) bv[j] = Vs[kk][tc*4+j];
#pragma unroll
            for (int i = 0; i < 4; i++)
#pragma unroll
                for (int j = 0; j < 4; j++)
                    acc[i][j] = fmaf(a[i], bv[j], acc[i][j]);
        }
        __syncthreads();
    }
#pragma unroll
    for (int i = 0; i < 4; i++)
#pragma unroll
        for (int j = 0; j < 4; j++)
            O[(size_t)(bb*Nc + i0 + tr*4 + i) * HDc + h*DHc + tc*4 + j] = acc[i][j];
}

// ===================================================================================
extern "C" void kernel_launch(void* const* d_in, const int* in_sizes, int n_in,
                              void* d_out, int out_size)
{
    const float* x_in    = (const float*)d_in[0];
    const float* r_t     = (const float*)d_in[1];
    const float* r_c     = (const float*)d_in[2];
    const float* r_p     = (const float*)d_in[3];
    const float* bias_pf = (const float*)d_in[4];
    const float* ln1_g   = (const float*)d_in[5];
    const float* ln1_b   = (const float*)d_in[6];
    const float* w_qkv   = (const float*)d_in[7];
    const float* w_out   = (const float*)d_in[8];
    const float* b_out   = (const float*)d_in[9];
    const float* w_kt    = (const float*)d_in[10];
    const float* w_kc    = (const float*)d_in[11];
    const float* w_kp    = (const float*)d_in[12];
    const float* ln2_g   = (const float*)d_in[13];
    const float* ln2_b   = (const float*)d_in[14];
    const float* w_ff1   = (const float*)d_in[15];
    const float* b_ff1   = (const float*)d_in[16];
    const float* w_ff2   = (const float*)d_in[17];
    const float* b_ff2   = (const float*)d_in[18];
    float* out = (float*)d_out;

    float *xn, *qkv, *q, *k, *v, *ws, *wsr, *ac, *bdraw, *av, *h1, *x, *xmid;
    cudaGetSymbolAddress((void**)&xn, g_xn);
    cudaGetSymbolAddress((void**)&qkv, g_qkv);
    cudaGetSymbolAddress((void**)&q, g_q);
    cudaGetSymbolAddress((void**)&k, g_k);
    cudaGetSymbolAddress((void**)&v, g_v);
    cudaGetSymbolAddress((void**)&ws, g_ws);
    cudaGetSymbolAddress((void**)&wsr, g_wsr);
    cudaGetSymbolAddress((void**)&ac, g_ac);
    cudaGetSymbolAddress((void**)&bdraw, g_bdraw);
    cudaGetSymbolAddress((void**)&av, g_av);
    cudaGetSymbolAddress((void**)&h1, g_h1);
    cudaGetSymbolAddress((void**)&x, g_x);
    cudaGetSymbolAddress((void**)&xmid, g_xmid);

    float* x_out    = out;                        // (B,N,D) = 1048576 floats
    float* attn_out = out + (size_t)Mc * Dc;      // (B,H,N,N) = 16777216 floats

    const float* cur = x_in;
    for (int l = 0; l < 4; l++) {
        // LN1
        ln_kernel<<<Mc, 128>>>(cur, xn, ln1_g + l*Dc, ln1_b + l*Dc);
        // qkv = xn @ w_qkv[l]   (2048 x 1536, K=512)
        gemm_kernel<<<dim3(3*HDc/64, Mc/64), 256>>>(
            xn, w_qkv + (size_t)l*Dc*3*HDc, qkv, Mc, 3*HDc, Dc, nullptr, nullptr, 0);
        split_qkv_kernel<<<(BHc*Nc*DHc)/256, 256>>>(qkv, bias_pf, q, k, v);
        // ws = r_t@w_kt + r_c@w_kc + r_p@w_kp  (rel_shift is linear -> one BD GEMM)
        gemm_kernel<<<dim3(HDc/64, Mc/64), 256>>>(
            r_t, w_kt + (size_t)l*Dc*HDc, ws, Mc, HDc, Dc, nullptr, nullptr, 0);
        gemm_kernel<<<dim3(HDc/64, Mc/64), 256>>>(
            r_c, w_kc + (size_t)l*Dc*HDc, ws, Mc, HDc, Dc, nullptr, nullptr, 4);
        gemm_kernel<<<dim3(HDc/64, Mc/64), 256>>>(
            r_p, w_kp + (size_t)l*Dc*HDc, ws, Mc, HDc, Dc, nullptr, nullptr, 4);
        wsr_kernel<<<(BHc*Nc*DHc)/256, 256>>>(ws, wsr);
        // AC = Q K^T ; BDraw = Q Ws^T  (batched over 16 bh)
        attn_score_kernel<<<dim3(Nc/64, Nc/64, BHc), 256>>>(q, k, ac);
        attn_score_kernel<<<dim3(Nc/64, Nc/64, BHc), 256>>>(q, wsr, bdraw);
        // dots = (AC + rel_shift(BDraw)) * SCALE  (in place on ac)
        combine_kernel<<<(int)(((size_t)BHc*Nc*Nc)/256), 256>>>(ac, bdraw);
        // softmax over heads; last layer writes straight into d_out (b,h,i,j)
        float* attn = (l == 3) ? attn_out : ac;
        softmax_h_kernel<<<(int)(((size_t)Bc*Nc*Nc)/256), 256>>>(ac, attn);
        // O = attn @ V, fused reshape to (b,n,h*d)
        attn_v_kernel<<<dim3(Nc/64, BHc), 256>>>(attn, v, av);
        // x = O @ w_out + b_out + x
        gemm_kernel<<<dim3(Dc/64, Mc/64), 256>>>(
            av, w_out + (size_t)l*HDc*Dc, xmid, Mc, Dc, HDc, b_out + l*Dc, cur, 2);
        // LN2
        ln_kernel<<<Mc, 128>>>(xmid, xn, ln2_g + l*Dc, ln2_b + l*Dc);
        // h1 = gelu(xn @ w_ff1 + b_ff1)
        gemm_kernel<<<dim3(FFc/64, Mc/64), 256>>>(
            xn, w_ff1 + (size_t)l*Dc*FFc, h1, Mc, FFc, Dc, b_ff1 + l*FFc, nullptr, 3);
        // x = h1 @ w_ff2 + b_ff2 + xmid ; last layer writes straight into d_out
        float* xdst = (l == 3) ? x_out : x;
        gemm_kernel<<<dim3(Dc/64, Mc/64), 256>>>(
            h1, w_ff2 + (size_t)l*FFc*Dc, xdst, Mc, Dc, FFc, b_ff2 + l*Dc, xmid, 2);
        cur = x;
    }
}

// round 4
// speedup vs baseline: 3.0976x; 3.0976x over previous
#include <cuda_runtime.h>
#include <math.h>
#include <stdint.h>

#define Bc 2
#define Nc 1024
#define Dc 512
#define Hc 8
#define DHc 64
#define HDc 512
#define FFc 2048
#define Mc (Bc*Nc)     /* 2048 rows */
#define BHc (Bc*Hc)    /* 16 batch-heads */
#define SCALEc 0.125f
#define BK 16
#define PAD 4

// ---------------- device scratch (static; no cudaMalloc allowed) --------------------
static __device__ __align__(256) float g_xn[Mc*Dc];
static __device__ __align__(256) float g_qkv[Mc*3*HDc];
static __device__ __align__(256) float g_q[BHc*Nc*DHc];
static __device__ __align__(256) float g_k[BHc*Nc*DHc];
static __device__ __align__(256) float g_v[BHc*Nc*DHc];
static __device__ __align__(256) float g_rcat[Mc*3*Dc];          // [r_t|r_c|r_p] 2048x1536
static __device__ __align__(256) float g_wall[3*Dc*4*HDc];       // 1536 x 2048
static __device__ __align__(256) float g_wsall[Mc*4*HDc];        // 2048 x 2048
static __device__ __align__(256) float g_wsr[4*BHc*Nc*DHc];      // per-layer (b,h,n,d)/3
static __device__ __align__(256) float g_ac[(size_t)BHc*Nc*Nc];
static __device__ __align__(256) float g_bdraw[(size_t)BHc*Nc*Nc];
static __device__ __align__(256) float g_attn[(size_t)BHc*Nc*Nc];
static __device__ __align__(256) float g_av[Mc*HDc];
static __device__ __align__(256) float g_h1[Mc*FFc];
static __device__ __align__(256) float g_x[Mc*Dc];
static __device__ __align__(256) float g_xmid[Mc*Dc];

// ---------------- tf32 helpers ------------------------------------------------------
__device__ __forceinline__ unsigned f2tf(float x) {
    unsigned u; asm("cvt.rna.tf32.f32 %0, %1;" : "=r"(u) : "f"(x)); return u;
}
__device__ __forceinline__ void mma8(float* c, const unsigned* a, const unsigned* b) {
    asm volatile("mma.sync.aligned.m16n8k8.row.col.f32.tf32.tf32.f32 "
        "{%0,%1,%2,%3}, {%4,%5,%6,%7}, {%8,%9}, {%0,%1,%2,%3};"
        : "+f"(c[0]), "+f"(c[1]), "+f"(c[2]), "+f"(c[3])
        : "r"(a[0]), "r"(a[1]), "r"(a[2]), "r"(a[3]), "r"(b[0]), "r"(b[1]));
}

// ---------------- unified tf32 tensor-core GEMM -------------------------------------
// C(MxN) = A(MxK) @ op(B);  TB=false: B is KxN row-major; TB=true: B is NxK row-major.
// grid: (N/BN, M/BM, batch); per-z pointer strides sA/sB/sC.
// mode: 0 plain, 1 +bias, 2 +bias+resid, 3 +bias then exact gelu,
//       4 attn_v epilogue: C[(bb*Nc + r)*HDc + h*DHc + c], bh = blockIdx.z
template<int BM, int BN, int WM, int WN, bool TB>
__global__ __launch_bounds__(256) void tf32_gemm(
    const float* __restrict__ A, const float* __restrict__ B, float* __restrict__ C,
    int K, int lda, int ldb, int ldc,
    long long sA, long long sB, long long sC,
    const float* __restrict__ bias, const float* __restrict__ resid, int mode)
{
    constexpr int NWN = BN / WN;
    constexpr int MT = WM / 16;
    constexpr int NT = WN / 8;
    constexpr int IA = (BM * 4) / 256;
    constexpr int IB = (BN * 4) / 256;
    __shared__ unsigned As[2][BK][BM + PAD];
    __shared__ unsigned Bs[2][BK][BN + PAD];

    const float* Ab = A + (size_t)sA * blockIdx.z;
    const float* Bb = B + (size_t)sB * blockIdx.z;
    float* Cb = C + (size_t)sC * blockIdx.z;

    int tid = threadIdx.x;
    int lane = tid & 31, wid = tid >> 5;
    int wm = (wid / NWN) * WM, wn = (wid % NWN) * WN;
    int gid = lane >> 2, tig = lane & 3;
    int bm0 = blockIdx.y * BM, bn0 = blockIdx.x * BN;

    float acc[MT][NT][4];
#pragma unroll
    for (int i = 0; i < MT; i++)
#pragma unroll
        for (int j = 0; j < NT; j++)
#pragma unroll
            for (int t = 0; t < 4; t++) acc[i][j][t] = 0.f;

    float4 ra[IA], rb[IB];

    auto FETCH = [&](int k0) {
#pragma unroll
        for (int it = 0; it < IA; it++) {
            int idx = tid + it * 256;
            int m = idx >> 2, kc = (idx & 3) * 4;
            ra[it] = *(const float4*)(Ab + (size_t)(bm0 + m) * lda + k0 + kc);
        }
        if (!TB) {
#pragma unroll
            for (int it = 0; it < IB; it++) {
                int idx = tid + it * 256;
                int kr = idx / (BN / 4), n4 = (idx % (BN / 4)) * 4;
                rb[it] = *(const float4*)(Bb + (size_t)(k0 + kr) * ldb + bn0 + n4);
            }
        } else {
#pragma unroll
            for (int it = 0; it < IB; it++) {
                int idx = tid + it * 256;
                int n = idx >> 2, kc = (idx & 3) * 4;
                rb[it] = *(const float4*)(Bb + (size_t)(bn0 + n) * ldb + k0 + kc);
            }
        }
    };
    auto STORE = [&](int buf) {
#pragma unroll
        for (int it = 0; it < IA; it++) {
            int idx = tid + it * 256;
            int m = idx >> 2, kc = (idx & 3) * 4;
            As[buf][kc + 0][m] = f2tf(ra[it].x);
            As[buf][kc + 1][m] = f2tf(ra[it].y);
            As[buf][kc + 2][m] = f2tf(ra[it].z);
            As[buf][kc + 3][m] = f2tf(ra[it].w);
        }
        if (!TB) {
#pragma unroll
            for (int it = 0; it < IB; it++) {
                int idx = tid + it * 256;
                int kr = idx / (BN / 4), n4 = (idx % (BN / 4)) * 4;
                uint4 t;
                t.x = f2tf(rb[it].x); t.y = f2tf(rb[it].y);
                t.z = f2tf(rb[it].z); t.w = f2tf(rb[it].w);
                *(uint4*)&Bs[buf][kr][n4] = t;
            }
        } else {
#pragma unroll
            for (int it = 0; it < IB; it++) {
                int idx = tid + it * 256;
                int n = idx >> 2, kc = (idx & 3) * 4;
                Bs[buf][kc + 0][n] = f2tf(rb[it].x);
                Bs[buf][kc + 1][n] = f2tf(rb[it].y);
                Bs[buf][kc + 2][n] = f2tf(rb[it].z);
                Bs[buf][kc + 3][n] = f2tf(rb[it].w);
            }
        }
    };

    FETCH(0); STORE(0);
    __syncthreads();

    int nk = K / BK;
    for (int kt = 0; kt < nk; kt++) {
        int buf = kt & 1;
        if (kt + 1 < nk) FETCH((kt + 1) * BK);
#pragma unroll
        for (int ks = 0; ks < 2; ks++) {
            unsigned af[MT][4], bf[NT][2];
#pragma unroll
            for (int mt = 0; mt < MT; mt++) {
                int m = wm + mt * 16 + gid;
                af[mt][0] = As[buf][ks * 8 + tig][m];
                af[mt][1] = As[buf][ks * 8 + tig][m + 8];
                af[mt][2] = As[buf][ks * 8 + tig + 4][m];
                af[mt][3] = As[buf][ks * 8 + tig + 4][m + 8];
            }
#pragma unroll
            for (int nt = 0; nt < NT; nt++) {
                int n = wn + nt * 8 + gid;
                bf[nt][0] = Bs[buf][ks * 8 + tig][n];
                bf[nt][1] = Bs[buf][ks * 8 + tig + 4][n];
            }
#pragma unroll
            for (int mt = 0; mt < MT; mt++)
#pragma unroll
                for (int nt = 0; nt < NT; nt++)
                    mma8(acc[mt][nt], af[mt], bf[nt]);
        }
        if (kt + 1 < nk) STORE(buf ^ 1);
        __syncthreads();
    }

    // epilogue: acc[mt][nt] = {(r0,c0),(r0,c0+1),(r0+8,c0),(r0+8,c0+1)}
#pragma unroll
    for (int mt = 0; mt < MT; mt++) {
        int r0 = bm0 + wm + mt * 16 + gid;
#pragma unroll
        for (int nt = 0; nt < NT; nt++) {
            int c0 = bn0 + wn + nt * 8 + tig * 2;
#pragma unroll
            for (int half = 0; half < 2; half++) {
                int r = r0 + half * 8;
                float v0 = acc[mt][nt][half * 2 + 0];
                float v1 = acc[mt][nt][half * 2 + 1];
                if (mode == 4) {
                    int bb2 = blockIdx.z >> 3, h = blockIdx.z & 7;
                    size_t off = ((size_t)(bb2 * Nc + r)) * HDc + h * DHc + c0;
                    C[off] = v0; C[off + 1] = v1;
                } else {
                    size_t off = (size_t)r * ldc + c0;
                    if (mode == 1) { v0 += bias[c0]; v1 += bias[c0 + 1]; }
                    else if (mode == 2) { v0 += bias[c0] + resid[off]; v1 += bias[c0 + 1] + resid[off + 1]; }
                    else if (mode == 3) {
                        v0 += bias[c0]; v1 += bias[c0 + 1];
                        v0 = 0.5f * v0 * (1.f + erff(v0 * 0.70710678118654752f));
                        v1 = 0.5f * v1 * (1.f + erff(v1 * 0.70710678118654752f));
                    }
                    Cb[off] = v0; Cb[off + 1] = v1;
                }
            }
        }
    }
}

// ---------------- LayerNorm ---------------------------------------------------------
__global__ __launch_bounds__(128) void ln_kernel(
    const float* __restrict__ in, float* __restrict__ out,
    const float* __restrict__ g, const float* __restrict__ bta)
{
    int row = blockIdx.x;
    const float* xr = in + (size_t)row * Dc;
    float* orow = out + (size_t)row * Dc;
    int tid = threadIdx.x;
    float v[4]; float s = 0.f, ss = 0.f;
#pragma unroll
    for (int i = 0; i < 4; i++) { v[i] = xr[tid + i*128]; s += v[i]; ss += v[i]*v[i]; }
#pragma unroll
    for (int o = 16; o > 0; o >>= 1) {
        s  += __shfl_xor_sync(0xffffffffu, s, o);
        ss += __shfl_xor_sync(0xffffffffu, ss, o);
    }
    __shared__ float sh[8];
    int w = tid >> 5, lane = tid & 31;
    if (lane == 0) { sh[w] = s; sh[4+w] = ss; }
    __syncthreads();
    if (tid == 0) {
        float ts = sh[0]+sh[1]+sh[2]+sh[3];
        float tss = sh[4]+sh[5]+sh[6]+sh[7];
        sh[0] = ts; sh[1] = tss;
    }
    __syncthreads();
    float mean = sh[0] * (1.f/Dc);
    float var  = sh[1] * (1.f/Dc) - mean*mean;
    float inv  = rsqrtf(var + 1e-5f);
#pragma unroll
    for (int i = 0; i < 4; i++) {
        int c = tid + i*128;
        orow[c] = (v[i]-mean)*inv*g[c] + bta[c];
    }
}

// ---------------- split qkv -> (b,h,n,d), q gets +bias_pf ---------------------------
__global__ void split_qkv_kernel(
    const float* __restrict__ qkv, const float* __restrict__ bias_pf,
    float* __restrict__ q, float* __restrict__ k, float* __restrict__ v)
{
    int idx = blockIdx.x * blockDim.x + threadIdx.x;
    int d = idx & 63;
    int n = (idx >> 6) & (Nc - 1);
    int h = (idx >> 16) & 7;
    int b = idx >> 19;
    size_t src = ((size_t)(b*Nc + n)) * (3*HDc) + h*DHc + d;
    q[idx] = qkv[src] + bias_pf[h*DHc + d];
    k[idx] = qkv[src + HDc];
    v[idx] = qkv[src + 2*HDc];
}

// ---------------- build [r_t|r_c|r_p] (2048 x 1536) ---------------------------------
__global__ void rcat_kernel(const float* __restrict__ rt, const float* __restrict__ rc,
                            const float* __restrict__ rp, float* __restrict__ out)
{
    int idx = blockIdx.x * blockDim.x + threadIdx.x;  // 2048*1536
    int row = idx / 1536, c = idx % 1536;
    float v;
    if (c < 512)       v = rt[row*512 + c];
    else if (c < 1024) v = rc[row*512 + c - 512];
    else               v = rp[row*512 + c - 1024];
    out[idx] = v;
}

// ---------------- build stacked W (1536 x 2048): col block l = [wkt;wkc;wkp][l] -----
__global__ void wall_kernel(const float* __restrict__ wkt, const float* __restrict__ wkc,
                            const float* __restrict__ wkp, float* __restrict__ out)
{
    int idx = blockIdx.x * blockDim.x + threadIdx.x;  // 1536*2048
    int k = idx >> 11;
    int col = idx & 2047;
    int l = col >> 9, c = col & 511;
    float v;
    if (k < 512)       v = wkt[((size_t)l*512 + k) * 512 + c];
    else if (k < 1024) v = wkc[((size_t)l*512 + k - 512) * 512 + c];
    else               v = wkp[((size_t)l*512 + k - 1024) * 512 + c];
    out[idx] = v;
}

// ---------------- wsr for all layers: (l,b,h,n,d) = wsall[(b,n),(l,h,d)]/3 ----------
__global__ void wsr_all_kernel(const float* __restrict__ wsall, float* __restrict__ wsr)
{
    int idx = blockIdx.x * blockDim.x + threadIdx.x;  // 4 * 2^20
    int d = idx & 63;
    int n = (idx >> 6) & (Nc - 1);
    int h = (idx >> 16) & 7;
    int b = (idx >> 19) & 1;
    int l = idx >> 20;
    wsr[idx] = wsall[((size_t)(b*Nc + n)) * 2048 + l*512 + h*64 + d] * (1.0f/3.0f);
}

// ---------------- fused: dots=(AC+rel_shift(BD))*SCALE, softmax over heads ----------
__global__ void softmax_fused_kernel(const float* __restrict__ AC,
                                     const float* __restrict__ BD,
                                     float* __restrict__ attn)
{
    size_t idx = (size_t)blockIdx.x * blockDim.x + threadIdx.x;  // B*N*N = 2M
    int j = (int)(idx & (Nc - 1));
    int i = (int)((idx >> 10) & (Nc - 1));
    int b = (int)(idx >> 20);
    int f = i * Nc + j + Nc;
    int i2 = f / (Nc + 1);
    int jj = f - i2 * (Nc + 1);
    size_t bd_off = (size_t)i2 * Nc + (jj - 1);
    size_t base = ((size_t)b * Hc) * Nc * Nc + (size_t)i * Nc + j;
    const size_t stride = (size_t)Nc * Nc;
    float d[Hc];
#pragma unroll
    for (int h = 0; h < Hc; h++) {
        float bd = (jj == 0) ? 0.f : BD[((size_t)(b*Hc + h)) * stride + bd_off];
        d[h] = (AC[base + h*stride] + bd) * SCALEc;
    }
    float m = d[0];
#pragma unroll
    for (int h = 1; h < Hc; h++) m = fmaxf(m, d[h]);
    float s = 0.f;
#pragma unroll
    for (int h = 0; h < Hc; h++) { d[h] = expf(d[h] - m); s += d[h]; }
    float inv = 1.f / s;
#pragma unroll
    for (int h = 0; h < Hc; h++) attn[base + h*stride] = d[h] * inv;
}

// ===================================================================================
extern "C" void kernel_launch(void* const* d_in, const int* in_sizes, int n_in,
                              void* d_out, int out_size)
{
    const float* x_in    = (const float*)d_in[0];
    const float* r_t     = (const float*)d_in[1];
    const float* r_c     = (const float*)d_in[2];
    const float* r_p     = (const float*)d_in[3];
    const float* bias_pf = (const float*)d_in[4];
    const float* ln1_g   = (const float*)d_in[5];
    const float* ln1_b   = (const float*)d_in[6];
    const float* w_qkv   = (const float*)d_in[7];
    const float* w_out   = (const float*)d_in[8];
    const float* b_out   = (const float*)d_in[9];
    const float* w_kt    = (const float*)d_in[10];
    const float* w_kc    = (const float*)d_in[11];
    const float* w_kp    = (const float*)d_in[12];
    const float* ln2_g   = (const float*)d_in[13];
    const float* ln2_b   = (const float*)d_in[14];
    const float* w_ff1   = (const float*)d_in[15];
    const float* b_ff1   = (const float*)d_in[16];
    const float* w_ff2   = (const float*)d_in[17];
    const float* b_ff2   = (const float*)d_in[18];
    float* out = (float*)d_out;

    float *xn, *qkv, *q, *k, *v, *rcat, *wall, *wsall, *wsr, *ac, *bdraw, *attnb,
          *av, *h1, *x, *xmid;
    cudaGetSymbolAddress((void**)&xn, g_xn);
    cudaGetSymbolAddress((void**)&qkv, g_qkv);
    cudaGetSymbolAddress((void**)&q, g_q);
    cudaGetSymbolAddress((void**)&k, g_k);
    cudaGetSymbolAddress((void**)&v, g_v);
    cudaGetSymbolAddress((void**)&rcat, g_rcat);
    cudaGetSymbolAddress((void**)&wall, g_wall);
    cudaGetSymbolAddress((void**)&wsall, g_wsall);
    cudaGetSymbolAddress((void**)&wsr, g_wsr);
    cudaGetSymbolAddress((void**)&ac, g_ac);
    cudaGetSymbolAddress((void**)&bdraw, g_bdraw);
    cudaGetSymbolAddress((void**)&attnb, g_attn);
    cudaGetSymbolAddress((void**)&av, g_av);
    cudaGetSymbolAddress((void**)&h1, g_h1);
    cudaGetSymbolAddress((void**)&x, g_x);
    cudaGetSymbolAddress((void**)&xmid, g_xmid);

    float* x_out    = out;
    float* attn_out = out + (size_t)Mc * Dc;

    // ---- upfront: all-layer relative-projection GEMM (layer-independent) ----------
    rcat_kernel<<<(Mc*3*Dc)/256, 256>>>(r_t, r_c, r_p, rcat);
    wall_kernel<<<(3*Dc*2048)/256, 256>>>(w_kt, w_kc, w_kp, wall);
    tf32_gemm<128,128,64,32,false><<<dim3(16,16), 256>>>(
        rcat, wall, wsall, 3*Dc, 3*Dc, 2048, 2048, 0,0,0, nullptr, nullptr, 0);
    wsr_all_kernel<<<(4*BHc*Nc*DHc)/256, 256>>>(wsall, wsr);

    const float* cur = x_in;
    for (int l = 0; l < 4; l++) {
        // LN1
        ln_kernel<<<Mc, 128>>>(cur, xn, ln1_g + l*Dc, ln1_b + l*Dc);
        // qkv = xn @ w_qkv[l]  (2048 x 1536, K=512)
        tf32_gemm<128,128,64,32,false><<<dim3(12,16), 256>>>(
            xn, w_qkv + (size_t)l*Dc*3*HDc, qkv, Dc, Dc, 3*HDc, 3*HDc,
            0,0,0, nullptr, nullptr, 0);
        split_qkv_kernel<<<(BHc*Nc*DHc)/256, 256>>>(qkv, bias_pf, q, k, v);
        // AC = Q K^T ; BDraw = Q Wsr^T (batched NT over 16 bh each)
        tf32_gemm<128,128,64,32,true><<<dim3(8,8,BHc), 256>>>(
            q, k, ac, DHc, DHc, DHc, Nc,
            (long long)Nc*DHc, (long long)Nc*DHc, (long long)Nc*Nc,
            nullptr, nullptr, 0);
        tf32_gemm<128,128,64,32,true><<<dim3(8,8,BHc), 256>>>(
            q, wsr + (size_t)l*BHc*Nc*DHc, bdraw, DHc, DHc, DHc, Nc,
            (long long)Nc*DHc, (long long)Nc*DHc, (long long)Nc*Nc,
            nullptr, nullptr, 0);
        // fused combine + rel_shift + softmax-over-heads
        float* attn = (l == 3) ? attn_out : attnb;
        softmax_fused_kernel<<<(int)(((size_t)Bc*Nc*Nc)/256), 256>>>(ac, bdraw, attn);
        // O = attn @ V  (batched NN, custom epilogue into (b,n,h*d))
        tf32_gemm<128,64,32,32,false><<<dim3(1,8,BHc), 256>>>(
            attn, v, av, Nc, Nc, DHc, HDc,
            (long long)Nc*Nc, (long long)Nc*DHc, 0,
            nullptr, nullptr, 4);
        // x = O @ w_out + b_out + x
        tf32_gemm<64,128,32,32,false><<<dim3(4,32), 256>>>(
            av, w_out + (size_t)l*HDc*Dc, xmid, HDc, HDc, Dc, Dc,
            0,0,0, b_out + l*Dc, cur, 2);
        // LN2
        ln_kernel<<<Mc, 128>>>(xmid, xn, ln2_g + l*Dc, ln2_b + l*Dc);
        // h1 = gelu(xn @ w_ff1 + b_ff1)
        tf32_gemm<128,128,64,32,false><<<dim3(16,16), 256>>>(
            xn, w_ff1 + (size_t)l*Dc*FFc, h1, Dc, Dc, FFc, FFc,
            0,0,0, b_ff1 + l*FFc, nullptr, 3);
        // x = h1 @ w_ff2 + b_ff2 + xmid
        float* xdst = (l == 3) ? x_out : x;
        tf32_gemm<64,128,32,32,false><<<dim3(4,32), 256>>>(
            h1, w_ff2 + (size_t)l*FFc*Dc, xdst, FFc, FFc, Dc, Dc,
            0,0,0, b_ff2 + l*Dc, xmid, 2);
        cur = x;
    }
}